// round 9
// baseline (speedup 1.0000x reference)
#include <cuda_runtime.h>
#include <cuda_bf16.h>

#define E_ 64
#define A_ 8
#define L_ 2048
#define D_ 128
#define H_ 8
#define EA_ (E_*A_)
#define CHUNK_ 256
#define NC_ 8

typedef unsigned long long ull;

// ---------------- device scratch ----------------
__device__ float g_Wq_eff[386 * 128];
__device__ float g_Wk_eff[128 * 128];
__device__ float g_Wv_eff[129 * 128];
__device__ float g_wtil [EA_ * H_ * 128];
__device__ float g_pu[EA_ * NC_ * 1024];
__device__ float g_pm[EA_ * NC_ * 8];
__device__ float g_pd[EA_ * NC_ * 8];
__device__ int   g_cnt[EA_];

// ---------------- packed f32x2 helpers ----------
__device__ __forceinline__ ull pack2(float a, float b) {
    ull r; asm("mov.b64 %0, {%1, %2};" : "=l"(r)
               : "r"(__float_as_uint(a)), "r"(__float_as_uint(b)));
    return r;
}
__device__ __forceinline__ void unpack2(ull v, float& a, float& b) {
    unsigned int x, y;
    asm("mov.b64 {%0, %1}, %2;" : "=r"(x), "=r"(y) : "l"(v));
    a = __uint_as_float(x); b = __uint_as_float(y);
}
__device__ __forceinline__ ull fma2(ull a, ull b, ull c) {
    ull d; asm("fma.rn.f32x2 %0, %1, %2, %3;" : "=l"(d) : "l"(a), "l"(b), "l"(c));
    return d;
}
__device__ __forceinline__ ull mul2(ull a, ull b) {
    ull d; asm("mul.rn.f32x2 %0, %1, %2;" : "=l"(d) : "l"(a), "l"(b));
    return d;
}
__device__ __forceinline__ void cp_async16(unsigned int saddr, const void* g) {
    asm volatile("cp.async.cg.shared.global [%0], [%1], 16;" :: "r"(saddr), "l"(g));
}
__device__ __forceinline__ void cp_commit() { asm volatile("cp.async.commit_group;"); }
__device__ __forceinline__ void cp_wait2()  { asm volatile("cp.async.wait_group 2;"); }

// ---------------- setup 1: compose projection matrices -------------------
__global__ void setup_eff(const float* __restrict__ Wq_proj,
                          const float* __restrict__ Wk_proj,
                          const float* __restrict__ Wv_proj,
                          const float* __restrict__ Wq,
                          const float* __restrict__ Wk,
                          const float* __restrict__ Wv) {
    __shared__ float row[128];
    int r = blockIdx.x, t = threadIdx.x;
    const float* proj; const float* W; float* out;
    if (r < 386)      { proj = Wq_proj + r * 128;        W = Wq; out = g_Wq_eff + r * 128; }
    else if (r < 514) { proj = Wk_proj + (r - 386) * 128; W = Wk; out = g_Wk_eff + (r - 386) * 128; }
    else              { proj = Wv_proj + (r - 514) * 128; W = Wv; out = g_Wv_eff + (r - 514) * 128; }
    row[t] = proj[t];
    __syncthreads();
    int h = t >> 4, k = t & 15;
    const float* Wb = W + h * 2048 + k;
    float a0 = 0.f, a1 = 0.f, a2 = 0.f, a3 = 0.f;
    #pragma unroll 8
    for (int m = 0; m < 128; m += 4) {
        a0 += row[m]     * __ldg(Wb + m * 16);
        a1 += row[m + 1] * __ldg(Wb + (m + 1) * 16);
        a2 += row[m + 2] * __ldg(Wb + (m + 2) * 16);
        a3 += row[m + 3] * __ldg(Wb + (m + 3) * 16);
    }
    out[t] = (a0 + a1) + (a2 + a3);
}

// ---------------- setup 2: per-(e,a) query -> w-tilde + cnt reset --------
__global__ void setup_wtil(const float* __restrict__ gc,
                           const float* __restrict__ dep,
                           const float* __restrict__ tbd,
                           const float* __restrict__ loadv) {
    __shared__ float qin[386];
    __shared__ float qh[128];
    int ea = blockIdx.x, t = threadIdx.x;
    int e = ea >> 3, a = ea & 7;
    qin[t]       = gc [e * 128 + t];
    qin[128 + t] = dep[e * 128 + t];
    qin[256 + t] = tbd[e * 128 + t];
    if (t == 0) { qin[384] = loadv[e * 8 + a]; qin[385] = (float)a; g_cnt[ea] = 0; }
    __syncthreads();
    float a0 = 0.f, a1 = 0.f, a2 = 0.f, a3 = 0.f;
    #pragma unroll 4
    for (int j = 0; j < 384; j += 4) {
        a0 += qin[j]     * g_Wq_eff[j * 128 + t];
        a1 += qin[j + 1] * g_Wq_eff[(j + 1) * 128 + t];
        a2 += qin[j + 2] * g_Wq_eff[(j + 2) * 128 + t];
        a3 += qin[j + 3] * g_Wq_eff[(j + 3) * 128 + t];
    }
    a0 += qin[384] * g_Wq_eff[384 * 128 + t];
    a1 += qin[385] * g_Wq_eff[385 * 128 + t];
    qh[t] = (a0 + a1) + (a2 + a3);
    __syncthreads();
    int d = t;
    #pragma unroll
    for (int h = 0; h < 8; h++) {
        float w = 0.f;
        #pragma unroll
        for (int k = 0; k < 16; k++)
            w += qh[h * 16 + k] * g_Wk_eff[d * 128 + h * 16 + k];
        g_wtil[(ea * 8 + h) * 128 + d] = w * 0.25f;
    }
}

// ---------------- attention partial + fused combine ----------------------
// One CTA (128 thr, 4 warps) per (ea, chunk of 256 rows), occupancy 2.
// Warp-private cp.async pipeline; 4-row interleaved single-pass inner loop
// (one stage = one 4-row warp batch); 8 independent 8-deep score chains.
__global__ __launch_bounds__(128, 2)
void attn_part(const float* __restrict__ emb,
               const int*   __restrict__ lens,
               const float* __restrict__ Wo,
               float*       __restrict__ out) {
    __shared__ __align__(16) char sraw[24 * 1024];  // stage bufs, later aliased
    __shared__ float sm_m[4][8], sm_d[4][8], sm_scale[4][8];
    __shared__ float c_scale[NC_][8], c_den[8];
    __shared__ int s_last;

    int pc = blockIdx.x;
    int ea = pc >> 3, c = pc & 7;
    int a  = ea & 7;
    int len = lens[ea];
    len = max(1, min(len, L_));
    int c0 = c << 8;
    if (c0 >= len) return;
    int c1 = min(c0 + CHUNK_, len);
    int rows = c1 - c0;
    int nst = (rows + 15) >> 4;
    int nact = min(NC_, (len + CHUNK_ - 1) >> 8);

    int tid  = threadIdx.x;
    int warp = tid >> 5, lane = tid & 31;
    int h = lane >> 2, g = lane & 3;

    float* wbuf = (float*)(sraw + warp * 6144);      // 3 x 2KB slots
    unsigned int sb = (unsigned int)__cvta_generic_to_shared(wbuf);
    const char* base = (const char*)emb + (size_t)ea * (L_ * 512);

    #define ISSUE(S) do {                                                    \
        int s_ = (S);                                                        \
        if (s_ < nst) {                                                      \
            unsigned int sb_ = sb + (unsigned int)((s_ % 3) * 2048);         \
            _Pragma("unroll")                                                \
            for (int j_ = 0; j_ < 4; j_++) {                                 \
                int r_ = min(c0 + s_ * 16 + warp * 4 + j_, c1 - 1);          \
                cp_async16(sb_ + j_ * 512 + lane * 16,                       \
                           base + (size_t)r_ * 512 + lane * 16);             \
            }                                                                \
        }                                                                    \
        cp_commit();                                                         \
    } while (0)

    ull w2[16], u2[16];
    {
        const float* wb = g_wtil + (ea * 8 + h) * 128;
        #pragma unroll
        for (int i = 0; i < 8; i++) {
            ulonglong2 v = *(const ulonglong2*)(wb + i * 16 + g * 4);
            w2[2*i] = v.x; w2[2*i+1] = v.y;
        }
    }
    #pragma unroll
    for (int i = 0; i < 16; i++) u2[i] = 0ull;

    float m = -1e30f;
    float denom = 0.f;

    ISSUE(0); ISSUE(1); ISSUE(2);

    for (int s = 0; s < nst; s++) {
        cp_wait2();
        const float* sp0 = wbuf + (s % 3) * 512;
        int rb = s * 16 + warp * 4;

        if (rb < rows) {
            // ---- 4-row batch: load + 8 independent 8-deep score chains ----
            ull xr[4][16];
            ull sa[4][2];
            #pragma unroll
            for (int j = 0; j < 4; j++) { sa[j][0] = 0ull; sa[j][1] = 0ull; }
            #pragma unroll
            for (int i = 0; i < 8; i++) {
                #pragma unroll
                for (int j = 0; j < 4; j++) {
                    ulonglong2 v = *(const ulonglong2*)(sp0 + j * 128 + i * 16 + g * 4);
                    xr[j][2*i] = v.x; xr[j][2*i+1] = v.y;
                    sa[j][0] = fma2(v.x, w2[2*i],   sa[j][0]);
                    sa[j][1] = fma2(v.y, w2[2*i+1], sa[j][1]);
                }
            }
            float sv[4];
            #pragma unroll
            for (int j = 0; j < 4; j++) {
                float f0, f1, f2, f3;
                unpack2(sa[j][0], f0, f1);
                unpack2(sa[j][1], f2, f3);
                sv[j] = (f0 + f2) + (f1 + f3);
            }
            #pragma unroll
            for (int j = 0; j < 4; j++)
                sv[j] += __shfl_xor_sync(0xffffffffu, sv[j], 1);
            #pragma unroll
            for (int j = 0; j < 4; j++)
                sv[j] += __shfl_xor_sync(0xffffffffu, sv[j], 2);
            #pragma unroll
            for (int j = 0; j < 4; j++)
                if (rb + j >= rows) sv[j] = -1e30f;

            // one max-update branch per 4 rows
            float gm = fmaxf(fmaxf(sv[0], sv[1]), fmaxf(sv[2], sv[3]));
            if (gm > m) {
                float mn = gm + 32.0f;        // headroom: branch ~never again
                float sc = __expf(m - mn);
                denom *= sc;
                ull sc2 = pack2(sc, sc);
                #pragma unroll
                for (int i = 0; i < 16; i++) u2[i] = mul2(u2[i], sc2);
                m = mn;
            }

            // batched exp
            float p0 = __expf(sv[0] - m);
            float p1 = __expf(sv[1] - m);
            float p2f = __expf(sv[2] - m);
            float p3 = __expf(sv[3] - m);
            denom += (p0 + p1) + (p2f + p3);
            ull pp[4] = {pack2(p0, p0), pack2(p1, p1),
                         pack2(p2f, p2f), pack2(p3, p3)};

            // accumulate all 4 rows (x in registers)
            #pragma unroll
            for (int i = 0; i < 16; i++) {
                ull acc = u2[i];
                acc = fma2(pp[0], xr[0][i], acc);
                acc = fma2(pp[1], xr[1][i], acc);
                acc = fma2(pp[2], xr[2][i], acc);
                acc = fma2(pp[3], xr[3][i], acc);
                u2[i] = acc;
            }
        }
        ISSUE(s + 3);
    }

    // ---- stage buffers dead: alias for partial merge ----
    __syncthreads();
    float (*sm_u)[8][128] = (float (*)[8][128])sraw;
    {
        float* up = &sm_u[warp][h][0];
        #pragma unroll
        for (int i = 0; i < 8; i++) {
            float f0, f1, f2, f3;
            unpack2(u2[2*i],   f0, f1);
            unpack2(u2[2*i+1], f2, f3);
            *(float4*)(up + i * 16 + g * 4) = make_float4(f0, f1, f2, f3);
        }
        if (g == 0) { sm_m[warp][h] = m; sm_d[warp][h] = denom; }
    }
    __syncthreads();

    if (tid < 8) {
        int hh = tid;
        float mh = -1e30f;
        #pragma unroll
        for (int w = 0; w < 4; w++) mh = fmaxf(mh, sm_m[w][hh]);
        float dt = 0.f;
        #pragma unroll
        for (int w = 0; w < 4; w++) {
            float sc = __expf(sm_m[w][hh] - mh);
            sm_scale[w][hh] = sc;
            dt += sm_d[w][hh] * sc;
        }
        g_pm[pc * 8 + hh] = mh;
        g_pd[pc * 8 + hh] = dt;
    }
    __syncthreads();

    for (int idx = tid; idx < 1024; idx += 128) {
        int hh = idx >> 7, d = idx & 127;
        float acc = 0.f;
        #pragma unroll
        for (int w = 0; w < 4; w++) acc += sm_u[w][hh][d] * sm_scale[w][hh];
        g_pu[pc * 1024 + idx] = acc;
    }
    __syncthreads();

    if (tid == 0) {
        __threadfence();
        s_last = (atomicAdd(&g_cnt[ea], 1) == nact - 1) ? 1 : 0;
    }
    __syncthreads();
    if (!s_last) return;

    float* uf  = (float*)(sraw + 16384);
    float* ctx = (float*)(sraw + 20480);

    if (tid < 8) {
        int hh = tid;
        float M = -1e30f;
        for (int cc = 0; cc < nact; cc++)
            M = fmaxf(M, g_pm[(ea * NC_ + cc) * 8 + hh]);
        float dt = 0.f;
        for (int cc = 0; cc < nact; cc++) {
            float sc = __expf(g_pm[(ea * NC_ + cc) * 8 + hh] - M);
            c_scale[cc][hh] = sc;
            dt += g_pd[(ea * NC_ + cc) * 8 + hh] * sc;
        }
        c_den[hh] = dt;
    }
    __syncthreads();

    for (int idx = tid; idx < 1024; idx += 128) {
        int hh = idx >> 7;
        float acc = 0.f;
        for (int cc = 0; cc < nact; cc++)
            acc += g_pu[(ea * NC_ + cc) * 1024 + idx] * c_scale[cc][hh];
        uf[idx] = acc;
    }
    __syncthreads();

    {
        int hh = tid >> 4;
        float a0 = 0.f, a1 = 0.f;
        #pragma unroll 8
        for (int d = 0; d < 128; d += 2) {
            a0 += uf[hh * 128 + d]     * g_Wv_eff[d * 128 + tid];
            a1 += uf[hh * 128 + d + 1] * g_Wv_eff[(d + 1) * 128 + tid];
        }
        ctx[tid] = (a0 + a1) / c_den[hh] + (float)a * g_Wv_eff[128 * 128 + tid];
    }
    __syncthreads();

    {
        float a0 = 0.f, a1 = 0.f;
        #pragma unroll 8
        for (int j = 0; j < 128; j += 2) {
            a0 += ctx[j]     * __ldg(Wo + j * 128 + tid);
            a1 += ctx[j + 1] * __ldg(Wo + (j + 1) * 128 + tid);
        }
        out[ea * 128 + tid] = a0 + a1;
    }
    #undef ISSUE
}

// ---------------- launch ------------------------------------------------
extern "C" void kernel_launch(void* const* d_in, const int* in_sizes, int n_in,
                              void* d_out, int out_size) {
    const float* gc      = (const float*)d_in[0];
    const float* dep     = (const float*)d_in[1];
    const float* tbd     = (const float*)d_in[2];
    const float* loadv   = (const float*)d_in[3];
    const float* emb     = (const float*)d_in[4];
    const int*   lens    = (const int*)  d_in[5];
    const float* Wq_proj = (const float*)d_in[6];
    const float* Wk_proj = (const float*)d_in[7];
    const float* Wv_proj = (const float*)d_in[8];
    const float* Wq      = (const float*)d_in[9];
    const float* Wk      = (const float*)d_in[10];
    const float* Wv      = (const float*)d_in[11];
    const float* Wo      = (const float*)d_in[12];
    float* out = (float*)d_out;

    setup_eff <<<643, 128>>>(Wq_proj, Wk_proj, Wv_proj, Wq, Wk, Wv);
    setup_wtil<<<EA_, 128>>>(gc, dep, tbd, loadv);
    attn_part <<<EA_ * NC_, 128>>>(emb, lens, Wo, out);
}

// round 11
// speedup vs baseline: 1.0458x; 1.0458x over previous
#include <cuda_runtime.h>
#include <cuda_bf16.h>

#define E_ 64
#define A_ 8
#define L_ 2048
#define D_ 128
#define H_ 8
#define EA_ (E_*A_)
#define CHUNK_ 256
#define NC_ 8

typedef unsigned long long ull;

// ---------------- device scratch ----------------
__device__ float g_Wq_eff[386 * 128];
__device__ float g_Wk_eff[128 * 128];
__device__ float g_Wv_eff[129 * 128];
__device__ float g_wtil [EA_ * H_ * 128];
__device__ float g_pu[EA_ * NC_ * 1024];
__device__ float g_pm[EA_ * NC_ * 8];
__device__ float g_pd[EA_ * NC_ * 8];
__device__ int   g_cnt[EA_];

// ---------------- packed f32x2 helpers ----------
__device__ __forceinline__ ull pack2(float a, float b) {
    ull r; asm("mov.b64 %0, {%1, %2};" : "=l"(r)
               : "r"(__float_as_uint(a)), "r"(__float_as_uint(b)));
    return r;
}
__device__ __forceinline__ void unpack2(ull v, float& a, float& b) {
    unsigned int x, y;
    asm("mov.b64 {%0, %1}, %2;" : "=r"(x), "=r"(y) : "l"(v));
    a = __uint_as_float(x); b = __uint_as_float(y);
}
__device__ __forceinline__ ull fma2(ull a, ull b, ull c) {
    ull d; asm("fma.rn.f32x2 %0, %1, %2, %3;" : "=l"(d) : "l"(a), "l"(b), "l"(c));
    return d;
}
__device__ __forceinline__ ull mul2(ull a, ull b) {
    ull d; asm("mul.rn.f32x2 %0, %1, %2;" : "=l"(d) : "l"(a), "l"(b));
    return d;
}
__device__ __forceinline__ void cp_async16(unsigned int saddr, const void* g) {
    asm volatile("cp.async.cg.shared.global [%0], [%1], 16;" :: "r"(saddr), "l"(g));
}
__device__ __forceinline__ void cp_commit() { asm volatile("cp.async.commit_group;"); }
__device__ __forceinline__ void cp_wait3()  { asm volatile("cp.async.wait_group 3;"); }

// ---------------- setup 1: compose projection matrices -------------------
__global__ void setup_eff(const float* __restrict__ Wq_proj,
                          const float* __restrict__ Wk_proj,
                          const float* __restrict__ Wv_proj,
                          const float* __restrict__ Wq,
                          const float* __restrict__ Wk,
                          const float* __restrict__ Wv) {
    __shared__ float row[128];
    int r = blockIdx.x, t = threadIdx.x;
    const float* proj; const float* W; float* out;
    if (r < 386)      { proj = Wq_proj + r * 128;        W = Wq; out = g_Wq_eff + r * 128; }
    else if (r < 514) { proj = Wk_proj + (r - 386) * 128; W = Wk; out = g_Wk_eff + (r - 386) * 128; }
    else              { proj = Wv_proj + (r - 514) * 128; W = Wv; out = g_Wv_eff + (r - 514) * 128; }
    row[t] = proj[t];
    __syncthreads();
    int h = t >> 4, k = t & 15;
    const float* Wb = W + h * 2048 + k;
    float a0 = 0.f, a1 = 0.f, a2 = 0.f, a3 = 0.f;
    #pragma unroll 8
    for (int m = 0; m < 128; m += 4) {
        a0 += row[m]     * __ldg(Wb + m * 16);
        a1 += row[m + 1] * __ldg(Wb + (m + 1) * 16);
        a2 += row[m + 2] * __ldg(Wb + (m + 2) * 16);
        a3 += row[m + 3] * __ldg(Wb + (m + 3) * 16);
    }
    out[t] = (a0 + a1) + (a2 + a3);
}

// ---------------- setup 2: per-(e,a) query -> w-tilde + cnt reset --------
__global__ void setup_wtil(const float* __restrict__ gc,
                           const float* __restrict__ dep,
                           const float* __restrict__ tbd,
                           const float* __restrict__ loadv) {
    __shared__ float qin[386];
    __shared__ float qh[128];
    int ea = blockIdx.x, t = threadIdx.x;
    int e = ea >> 3, a = ea & 7;
    qin[t]       = gc [e * 128 + t];
    qin[128 + t] = dep[e * 128 + t];
    qin[256 + t] = tbd[e * 128 + t];
    if (t == 0) { qin[384] = loadv[e * 8 + a]; qin[385] = (float)a; g_cnt[ea] = 0; }
    __syncthreads();
    float a0 = 0.f, a1 = 0.f, a2 = 0.f, a3 = 0.f;
    #pragma unroll 4
    for (int j = 0; j < 384; j += 4) {
        a0 += qin[j]     * g_Wq_eff[j * 128 + t];
        a1 += qin[j + 1] * g_Wq_eff[(j + 1) * 128 + t];
        a2 += qin[j + 2] * g_Wq_eff[(j + 2) * 128 + t];
        a3 += qin[j + 3] * g_Wq_eff[(j + 3) * 128 + t];
    }
    a0 += qin[384] * g_Wq_eff[384 * 128 + t];
    a1 += qin[385] * g_Wq_eff[385 * 128 + t];
    qh[t] = (a0 + a1) + (a2 + a3);
    __syncthreads();
    int d = t;
    #pragma unroll
    for (int h = 0; h < 8; h++) {
        float w = 0.f;
        #pragma unroll
        for (int k = 0; k < 16; k++)
            w += qh[h * 16 + k] * g_Wk_eff[d * 128 + h * 16 + k];
        g_wtil[(ea * 8 + h) * 128 + d] = w * 0.25f;
    }
}

// ---------------- attention partial + fused combine ----------------------
// One CTA (128 thr, 4 warps) per (ea, chunk of 256 rows), occupancy 4
// (<=128 regs). Warp-private 4-deep cp.async pipeline; single-row inner
// loop (register diet for 16 warps/SM).
__global__ __launch_bounds__(128, 4)
void attn_part(const float* __restrict__ emb,
               const int*   __restrict__ lens,
               const float* __restrict__ Wo,
               float*       __restrict__ out) {
    __shared__ __align__(16) char sraw[32 * 1024];  // 4 warps x 4 stages x 2KB
    __shared__ float sm_m[4][8], sm_d[4][8], sm_scale[4][8];
    __shared__ float c_scale[NC_][8], c_den[8];
    __shared__ int s_last;

    int pc = blockIdx.x;
    int ea = pc >> 3;
    int len = lens[ea];
    len = max(1, min(len, L_));
    int c0 = (pc & 7) << 8;
    if (c0 >= len) return;
    int rows = min(c0 + CHUNK_, len) - c0;
    int nst = (rows + 15) >> 4;

    int tid  = threadIdx.x;
    int warp = tid >> 5, lane = tid & 31;
    int h = lane >> 2, g = lane & 3;

    // warp-private stage buffers: 4 slots of 2KB
    float* wbuf = (float*)(sraw + warp * 8192);
    // per-lane smem base: includes lane's 16B offset (matches gbase)
    unsigned int sb = (unsigned int)__cvta_generic_to_shared(wbuf) + lane * 16;
    // per-lane global base: row 0 of this chunk, +lane*16B
    const char* gbase = (const char*)emb + (size_t)ea * (L_ * 512)
                      + (size_t)c0 * 512 + lane * 16;
    int rmax = rows - 1;   // clamp in chunk-local row units

    // stage s covers chunk-rows [s*16, s*16+16); warp owns 4 of them
    #define ISSUE(S) do {                                                    \
        int s_ = (S);                                                        \
        if (s_ < nst) {                                                      \
            unsigned int sb_ = sb + (unsigned int)((s_ & 3) << 11);          \
            int rbw_ = s_ * 16 + warp * 4;                                   \
            _Pragma("unroll")                                                \
            for (int j_ = 0; j_ < 4; j_++) {                                 \
                int r_ = min(rbw_ + j_, rmax);                               \
                cp_async16(sb_ + j_ * 512, gbase + (size_t)r_ * 512);        \
            }                                                                \
        }                                                                    \
        cp_commit();                                                         \
    } while (0)

    ull w2[16], u2[16];
    {
        const float* wb = g_wtil + (ea * 8 + h) * 128;
        #pragma unroll
        for (int i = 0; i < 8; i++) {
            ulonglong2 v = *(const ulonglong2*)(wb + i * 16 + g * 4);
            w2[2*i] = v.x; w2[2*i+1] = v.y;
        }
    }
    #pragma unroll
    for (int i = 0; i < 16; i++) u2[i] = 0ull;

    float m = -1e30f;
    float denom = 0.f;

    ISSUE(0); ISSUE(1); ISSUE(2); ISSUE(3);

    for (int s = 0; s < nst; s++) {
        cp_wait3();
        const float* sp0 = wbuf + ((s & 3) << 9);
        int rb = s * 16 + warp * 4;
        #pragma unroll
        for (int j = 0; j < 4; j++) {
            if (rb + j < rows) {
                const float* sp = sp0 + j * 128;
                ull x2[16];
                #pragma unroll
                for (int i = 0; i < 8; i++) {
                    ulonglong2 v = *(const ulonglong2*)(sp + i * 16 + g * 4);
                    x2[2*i] = v.x; x2[2*i+1] = v.y;
                }
                // two independent 8-deep score chains
                ull a0 = 0ull, a1 = 0ull;
                #pragma unroll
                for (int i = 0; i < 8; i++) {
                    a0 = fma2(x2[2*i],   w2[2*i],   a0);
                    a1 = fma2(x2[2*i+1], w2[2*i+1], a1);
                }
                float f0, f1, f2, f3;
                unpack2(a0, f0, f1); unpack2(a1, f2, f3);
                float sv = (f0 + f2) + (f1 + f3);
                sv += __shfl_xor_sync(0xffffffffu, sv, 1);
                sv += __shfl_xor_sync(0xffffffffu, sv, 2);
                float p;
                if (sv > m) {                 // rare (32-headroom)
                    float mn = sv + 32.0f;
                    float sc = __expf(m - mn);
                    denom *= sc;
                    ull sc2 = pack2(sc, sc);
                    #pragma unroll
                    for (int i = 0; i < 16; i++) u2[i] = mul2(u2[i], sc2);
                    m = mn;
                    p = 1.26641655e-14f;      // exp(-32)
                } else {
                    p = __expf(sv - m);
                }
                denom += p;
                ull p2 = pack2(p, p);
                #pragma unroll
                for (int i = 0; i < 16; i++) u2[i] = fma2(p2, x2[i], u2[i]);
            }
        }
        ISSUE(s + 4);
    }

    // ---- stage buffers dead: alias for partial merge ----
    __syncthreads();
    float (*sm_u)[8][128] = (float (*)[8][128])sraw;   // 16KB
    {
        float* up = &sm_u[warp][h][0];
        #pragma unroll
        for (int i = 0; i < 8; i++) {
            float f0, f1, f2, f3;
            unpack2(u2[2*i],   f0, f1);
            unpack2(u2[2*i+1], f2, f3);
            *(float4*)(up + i * 16 + g * 4) = make_float4(f0, f1, f2, f3);
        }
        if (g == 0) { sm_m[warp][h] = m; sm_d[warp][h] = denom; }
    }
    __syncthreads();

    if (tid < 8) {
        int hh = tid;
        float mh = -1e30f;
        #pragma unroll
        for (int w = 0; w < 4; w++) mh = fmaxf(mh, sm_m[w][hh]);
        float dt = 0.f;
        #pragma unroll
        for (int w = 0; w < 4; w++) {
            float sc = __expf(sm_m[w][hh] - mh);
            sm_scale[w][hh] = sc;
            dt += sm_d[w][hh] * sc;
        }
        g_pm[pc * 8 + hh] = mh;
        g_pd[pc * 8 + hh] = dt;
    }
    __syncthreads();

    for (int idx = tid; idx < 1024; idx += 128) {
        int hh = idx >> 7, d = idx & 127;
        float acc = 0.f;
        #pragma unroll
        for (int w = 0; w < 4; w++) acc += sm_u[w][hh][d] * sm_scale[w][hh];
        g_pu[pc * 1024 + idx] = acc;
    }
    __syncthreads();

    int nact = min(NC_, (len + CHUNK_ - 1) >> 8);
    if (tid == 0) {
        __threadfence();
        s_last = (atomicAdd(&g_cnt[ea], 1) == nact - 1) ? 1 : 0;
    }
    __syncthreads();
    if (!s_last) return;

    float* uf  = (float*)(sraw + 16384);
    float* ctx = (float*)(sraw + 20480);

    if (tid < 8) {
        int hh = tid;
        float M = -1e30f;
        for (int cc = 0; cc < nact; cc++)
            M = fmaxf(M, g_pm[(ea * NC_ + cc) * 8 + hh]);
        float dt = 0.f;
        for (int cc = 0; cc < nact; cc++) {
            float sc = __expf(g_pm[(ea * NC_ + cc) * 8 + hh] - M);
            c_scale[cc][hh] = sc;
            dt += g_pd[(ea * NC_ + cc) * 8 + hh] * sc;
        }
        c_den[hh] = dt;
    }
    __syncthreads();

    for (int idx = tid; idx < 1024; idx += 128) {
        int hh = idx >> 7;
        float acc = 0.f;
        for (int cc = 0; cc < nact; cc++)
            acc += g_pu[(ea * NC_ + cc) * 1024 + idx] * c_scale[cc][hh];
        uf[idx] = acc;
    }
    __syncthreads();

    {
        int hh = tid >> 4;
        float a0 = 0.f, a1 = 0.f;
        #pragma unroll 8
        for (int d = 0; d < 128; d += 2) {
            a0 += uf[hh * 128 + d]     * g_Wv_eff[d * 128 + tid];
            a1 += uf[hh * 128 + d + 1] * g_Wv_eff[(d + 1) * 128 + tid];
        }
        ctx[tid] = (a0 + a1) / c_den[hh]
                 + (float)(ea & 7) * g_Wv_eff[128 * 128 + tid];
    }
    __syncthreads();

    {
        float a0 = 0.f, a1 = 0.f;
        #pragma unroll 8
        for (int j = 0; j < 128; j += 2) {
            a0 += ctx[j]     * __ldg(Wo + j * 128 + tid);
            a1 += ctx[j + 1] * __ldg(Wo + (j + 1) * 128 + tid);
        }
        out[ea * 128 + tid] = a0 + a1;
    }
    #undef ISSUE
}

// ---------------- launch ------------------------------------------------
extern "C" void kernel_launch(void* const* d_in, const int* in_sizes, int n_in,
                              void* d_out, int out_size) {
    const float* gc      = (const float*)d_in[0];
    const float* dep     = (const float*)d_in[1];
    const float* tbd     = (const float*)d_in[2];
    const float* loadv   = (const float*)d_in[3];
    const float* emb     = (const float*)d_in[4];
    const int*   lens    = (const int*)  d_in[5];
    const float* Wq_proj = (const float*)d_in[6];
    const float* Wk_proj = (const float*)d_in[7];
    const float* Wv_proj = (const float*)d_in[8];
    const float* Wq      = (const float*)d_in[9];
    const float* Wk      = (const float*)d_in[10];
    const float* Wv      = (const float*)d_in[11];
    const float* Wo      = (const float*)d_in[12];
    float* out = (float*)d_out;

    setup_eff <<<643, 128>>>(Wq_proj, Wk_proj, Wv_proj, Wq, Wk, Wv);
    setup_wtil<<<EA_, 128>>>(gc, dep, tbd, loadv);
    attn_part <<<EA_ * NC_, 128>>>(emb, lens, Wo, out);
}